// round 6
// baseline (speedup 1.0000x reference)
#include <cuda_runtime.h>
#include <cstdint>

// CBOW negative-sampling loss. cp.async.bulk gather staging -> smem.
// Shapes (fixed): B=16384, C=10, K=8, D=128, VOCAB=100000.
// d_in: contexts[B,C] i32, focus_word[B,K] i32, weight_mask[B,K] f32,
//       labels[B,K] f32, ctx_emb[V,D] f32, neg_emb[V,D] f32.
// d_out: 1 float (batch-mean loss).

#define B_N 16384
#define C_N 10
#define K_N 8
#define R_N (C_N + K_N)              // 18 rows per example
#define D_N 128
#define ROW_BYTES (D_N * 4)          // 512
#define WARPS_PER_BLOCK 4
#define THREADS (WARPS_PER_BLOCK * 32)   // 128
#define NBLOCKS (B_N / WARPS_PER_BLOCK)  // 4096

__device__ float        g_partials[NBLOCKS];
__device__ unsigned int g_count;     // zero-init; self-resetting each run

__device__ __forceinline__ uint32_t smem_u32(const void* p) {
    uint32_t a;
    asm("{ .reg .u64 t; cvta.to.shared.u64 t, %1; cvt.u32.u64 %0, t; }"
        : "=r"(a) : "l"(p));
    return a;
}

__global__ __launch_bounds__(THREADS)
void cbow_loss_kernel(const int*   __restrict__ contexts,
                      const int*   __restrict__ focus,
                      const float* __restrict__ wmask,
                      const float* __restrict__ labels,
                      const float* __restrict__ ctx_emb,
                      const float* __restrict__ neg_emb,
                      float*       __restrict__ out)
{
    // 4 warps x 18 rows x 512B = 36 KB staged rows + per-warp mbarrier.
    __shared__ __align__(16) float    rows[WARPS_PER_BLOCK][R_N][D_N];
    __shared__ __align__(8)  uint64_t mbar[WARPS_PER_BLOCK];

    const int warp = threadIdx.x >> 5;
    const int lane = threadIdx.x & 31;
    const int b    = blockIdx.x * WARPS_PER_BLOCK + warp;
    const unsigned FULL = 0xffffffffu;

    const uint32_t row_base  = smem_u32(&rows[warp][0][0]);
    const uint32_t mbar_addr = smem_u32(&mbar[warp]);

    // ---- mbarrier init (1 arrival: the expect_tx) ----
    if (lane == 0) {
        asm volatile("mbarrier.init.shared.b64 [%0], %1;"
                     :: "r"(mbar_addr), "r"(1u) : "memory");
        asm volatile("fence.proxy.async.shared::cta;" ::: "memory");
    }
    __syncwarp();
    if (lane == 0) {
        asm volatile("mbarrier.arrive.expect_tx.shared.b64 _, [%0], %1;"
                     :: "r"(mbar_addr), "r"((unsigned)(R_N * ROW_BYTES)) : "memory");
    }
    __syncwarp();   // expect_tx set before any completion can land

    // ---- lanes 0..17: one register-free bulk gather each ----
    if (lane < R_N) {
        const int idx = (lane < C_N)
                      ? __ldg(&contexts[b * C_N + lane])
                      : __ldg(&focus[b * K_N + (lane - C_N)]);
        const float* src = (lane < C_N)
                         ? ctx_emb + (size_t)idx * D_N
                         : neg_emb + (size_t)idx * D_N;
        const uint32_t dst = row_base + (uint32_t)lane * ROW_BYTES;
        asm volatile(
            "cp.async.bulk.shared::cluster.global.mbarrier::complete_tx::bytes "
            "[%0], [%1], %2, [%3];"
            :: "r"(dst), "l"(src), "r"((unsigned)ROW_BYTES), "r"(mbar_addr)
            : "memory");
    }

    // ---- wait for all 18 rows (acquire orders subsequent smem reads) ----
    {
        uint32_t done;
        asm volatile(
            "{\n\t.reg .pred p;\n\t"
            "mbarrier.try_wait.parity.acquire.cta.shared::cta.b64 p, [%1], 0;\n\t"
            "selp.b32 %0, 1, 0, p;\n\t}"
            : "=r"(done) : "r"(mbar_addr) : "memory");
        if (!done) {
            asm volatile(
                "{\n\t.reg .pred p;\n\t"
                "W%=:\n\t"
                "mbarrier.try_wait.parity.acquire.cta.shared::cta.b64 p, [%0], 0, 0x989680;\n\t"
                "@p bra D%=;\n\t"
                "bra W%=;\n\t"
                "D%=:\n\t}"
                :: "r"(mbar_addr) : "memory");
        }
    }

    // ---- sum-pool 10 context rows from smem; lane owns 4 columns ----
    float4 src4 = make_float4(0.f, 0.f, 0.f, 0.f);
#pragma unroll
    for (int c = 0; c < C_N; c++) {
        const float4 v = *reinterpret_cast<const float4*>(&rows[warp][c][lane * 4]);
        src4.x += v.x; src4.y += v.y; src4.z += v.z; src4.w += v.w;
    }

    // ---- 8 per-lane partial dots from smem ----
    float pred[K_N];
#pragma unroll
    for (int k = 0; k < K_N; k++) {
        const float4 t = *reinterpret_cast<const float4*>(&rows[warp][C_N + k][lane * 4]);
        pred[k] = src4.x * t.x + src4.y * t.y + src4.z * t.z + src4.w * t.w;
    }

    // ---- packed multi-reduce: 8 reductions in 9 shuffles ----
    float c4[4];
#pragma unroll
    for (int j = 0; j < 4; j++) {
        const bool lo = (lane & 16) == 0;
        const float keep = lo ? pred[2 * j] : pred[2 * j + 1];
        const float send = lo ? pred[2 * j + 1] : pred[2 * j];
        c4[j] = keep + __shfl_xor_sync(FULL, send, 16);
    }
    float e2[2];
#pragma unroll
    for (int j = 0; j < 2; j++) {
        const bool lo = (lane & 8) == 0;
        const float keep = lo ? c4[2 * j] : c4[2 * j + 1];
        const float send = lo ? c4[2 * j + 1] : c4[2 * j];
        e2[j] = keep + __shfl_xor_sync(FULL, send, 8);
    }
    float f;
    {
        const bool lo = (lane & 4) == 0;
        const float keep = lo ? e2[0] : e2[1];
        const float send = lo ? e2[1] : e2[0];
        f = keep + __shfl_xor_sync(FULL, send, 4);
    }
    f += __shfl_xor_sync(FULL, f, 2);
    f += __shfl_xor_sync(FULL, f, 1);
    const int k = ((lane >> 4) & 1) | (((lane >> 3) & 1) << 1) | (((lane >> 2) & 1) << 2);

    // ---- per-lane weighted BCE term (each k on 4 lanes; dup cancels) ----
    const float w = __ldg(&wmask[b * K_N + k]);
    const float y = __ldg(&labels[b * K_N + k]);
    const float lae = fmaxf(f, 0.f) + log1pf(__expf(-fabsf(f)));
    const float bce = w * (lae - f * y);

    // ---- packed pair-reduce: sum(bce) lower half, sum(w) upper ----
    float r;
    {
        const bool lo = lane < 16;
        const float keep = lo ? bce : w;
        const float send = lo ? w : bce;
        r = keep + __shfl_xor_sync(FULL, send, 16);
    }
#pragma unroll
    for (int off = 8; off; off >>= 1)
        r += __shfl_xor_sync(FULL, r, off);
    const float wtot = __shfl_sync(FULL, r, 16);

    // ---- deterministic block partial ----
    __shared__ float ws[WARPS_PER_BLOCK];
    __shared__ bool  is_last;
    if (lane == 0) ws[warp] = r / wtot;
    __syncthreads();
    if (threadIdx.x == 0) {
        float s = 0.f;
#pragma unroll
        for (int i = 0; i < WARPS_PER_BLOCK; i++) s += ws[i];
        g_partials[blockIdx.x] = s;
        unsigned prev;
        asm volatile("atom.acq_rel.gpu.global.add.u32 %0, [%1], %2;"
                     : "=r"(prev)
                     : "l"(&g_count), "r"(1u)
                     : "memory");
        is_last = (prev == (unsigned)(NBLOCKS - 1));
    }
    __syncthreads();

    // ---- last block: deterministic final reduction + counter reset ----
    if (is_last) {
        const int tid = threadIdx.x;               // 128 threads, 4096 partials
        float v = 0.f;
#pragma unroll
        for (int j = 0; j < NBLOCKS / THREADS; j++)   // 32 fixed-order chunks
            v += __ldcg(&g_partials[tid + j * THREADS]);
#pragma unroll
        for (int off = 16; off; off >>= 1)
            v += __shfl_xor_sync(FULL, v, off);

        __shared__ float s2[WARPS_PER_BLOCK];
        if (lane == 0) s2[tid >> 5] = v;
        __syncthreads();
        if (tid < 32) {
            float z = (tid < WARPS_PER_BLOCK) ? s2[tid] : 0.f;
#pragma unroll
            for (int off = 2; off; off >>= 1)
                z += __shfl_xor_sync(FULL, z, off);
            if (tid == 0) {
                out[0]  = z * (1.0f / (float)B_N);
                g_count = 0u;                      // reset for next graph replay
            }
        }
    }
}

extern "C" void kernel_launch(void* const* d_in, const int* in_sizes, int n_in,
                              void* d_out, int out_size)
{
    const int*   contexts = (const int*)  d_in[0];
    const int*   focus    = (const int*)  d_in[1];
    const float* wmask    = (const float*)d_in[2];
    const float* labels   = (const float*)d_in[3];
    const float* ctx_emb  = (const float*)d_in[4];
    const float* neg_emb  = (const float*)d_in[5];
    float*       out      = (float*)d_out;

    cbow_loss_kernel<<<NBLOCKS, THREADS>>>(contexts, focus, wmask, labels,
                                           ctx_emb, neg_emb, out);
}

// round 7
// speedup vs baseline: 1.4151x; 1.4151x over previous
#include <cuda_runtime.h>

// CBOW negative-sampling loss, fused single-launch. 1 example/warp, LDG gathers.
// Shapes (fixed): B=16384, C=10, K=8, D=128, VOCAB=100000.
// d_in: contexts[B,C] i32, focus_word[B,K] i32, weight_mask[B,K] f32,
//       labels[B,K] f32, ctx_emb[V,D] f32, neg_emb[V,D] f32.
// d_out: 1 float (batch-mean loss).

#define B_N 16384
#define C_N 10
#define K_N 8
#define D_N 128
#define WARPS_PER_BLOCK 8
#define THREADS (WARPS_PER_BLOCK * 32)      // 256
#define NBLOCKS (B_N / WARPS_PER_BLOCK)     // 2048

__device__ float        g_partials[NBLOCKS];
__device__ unsigned int g_count;            // zero-init; self-resetting each run

__global__ __launch_bounds__(THREADS, 8)    // force regs<=32 -> 64 warps/SM
void cbow_loss_kernel(const int*   __restrict__ contexts,
                      const int*   __restrict__ focus,
                      const float* __restrict__ wmask,
                      const float* __restrict__ labels,
                      const float* __restrict__ ctx_emb,
                      const float* __restrict__ neg_emb,
                      float*       __restrict__ out)
{
    const int warp = threadIdx.x >> 5;
    const int lane = threadIdx.x & 31;
    const int b    = blockIdx.x * WARPS_PER_BLOCK + warp;
    const unsigned FULL = 0xffffffffu;

    // ---- ALL 18 indices in ONE lane-distributed LDG ----
    // lane 0..9   -> contexts[b][lane]
    // lane 10..27 -> focus[b][lane-10]   (only 10..17 used)
    // lane 28..31 -> focus[b][(lane-10)&7]  (harmless dup, keeps load valid)
    const int* ip = (lane < C_N)
                  ? contexts + b * C_N + lane
                  : focus + b * K_N + ((lane - C_N) & (K_N - 1));
    const int idx = __ldg(ip);

    // ---- sum-pool 10 context rows; lane owns 4 contiguous columns ----
    float4 src = make_float4(0.f, 0.f, 0.f, 0.f);
#pragma unroll
    for (int c = 0; c < C_N; c++) {
        const int i = __shfl_sync(FULL, idx, c);
        const float4 v =
            __ldg(reinterpret_cast<const float4*>(ctx_emb + (size_t)i * D_N) + lane);
        src.x += v.x; src.y += v.y; src.z += v.z; src.w += v.w;
    }

    // ---- 8 per-lane partial dots (independent LDG.128) ----
    float pred[K_N];
#pragma unroll
    for (int k = 0; k < K_N; k++) {
        const int j = __shfl_sync(FULL, idx, C_N + k);
        const float4 t =
            __ldg(reinterpret_cast<const float4*>(neg_emb + (size_t)j * D_N) + lane);
        pred[k] = src.x * t.x + src.y * t.y + src.z * t.z + src.w * t.w;
    }

    // ---- packed multi-reduce: 8 reductions in 9 shuffles ----
    // Lane bits 4,3,2 pick pred index; each lane ends with full dot for
    // k(lane) = bit4 | bit3<<1 | bit2<<2.
    float c4[4];
#pragma unroll
    for (int j = 0; j < 4; j++) {
        const bool lo = (lane & 16) == 0;
        const float keep = lo ? pred[2 * j] : pred[2 * j + 1];
        const float send = lo ? pred[2 * j + 1] : pred[2 * j];
        c4[j] = keep + __shfl_xor_sync(FULL, send, 16);
    }
    float e2[2];
#pragma unroll
    for (int j = 0; j < 2; j++) {
        const bool lo = (lane & 8) == 0;
        const float keep = lo ? c4[2 * j] : c4[2 * j + 1];
        const float send = lo ? c4[2 * j + 1] : c4[2 * j];
        e2[j] = keep + __shfl_xor_sync(FULL, send, 8);
    }
    float f;
    {
        const bool lo = (lane & 4) == 0;
        const float keep = lo ? e2[0] : e2[1];
        const float send = lo ? e2[1] : e2[0];
        f = keep + __shfl_xor_sync(FULL, send, 4);
    }
    f += __shfl_xor_sync(FULL, f, 2);
    f += __shfl_xor_sync(FULL, f, 1);
    const int k = ((lane >> 4) & 1) | (((lane >> 3) & 1) << 1) | (((lane >> 2) & 1) << 2);

    // ---- per-lane weighted BCE term (each k on 4 lanes; dup cancels) ----
    const float w = __ldg(&wmask[b * K_N + k]);
    const float y = __ldg(&labels[b * K_N + k]);
    const float lae = fmaxf(f, 0.f) + log1pf(__expf(-fabsf(f)));
    const float bce = w * (lae - f * y);

    // ---- packed pair-reduce: sum(bce) lower half, sum(w) upper ----
    float r;
    {
        const bool lo = lane < 16;
        const float keep = lo ? bce : w;
        const float send = lo ? w : bce;
        r = keep + __shfl_xor_sync(FULL, send, 16);
    }
#pragma unroll
    for (int off = 8; off; off >>= 1)
        r += __shfl_xor_sync(FULL, r, off);
    const float wtot = __shfl_sync(FULL, r, 16);   // sum(w)*4 / matches bce*4

    // ---- deterministic block partial ----
    __shared__ float ws[WARPS_PER_BLOCK];
    __shared__ bool  is_last;
    if (lane == 0) ws[warp] = r / wtot;
    __syncthreads();
    if (threadIdx.x == 0) {
        float s = 0.f;
#pragma unroll
        for (int i = 0; i < WARPS_PER_BLOCK; i++) s += ws[i];
        g_partials[blockIdx.x] = s;
        unsigned prev;
        asm volatile("atom.acq_rel.gpu.global.add.u32 %0, [%1], %2;"
                     : "=r"(prev)
                     : "l"(&g_count), "r"(1u)
                     : "memory");
        is_last = (prev == (unsigned)(NBLOCKS - 1));
    }
    __syncthreads();

    // ---- last block: deterministic final reduction + counter reset ----
    if (is_last) {
        const int tid = threadIdx.x;               // 256 threads, 2048 partials
        float v = 0.f;
#pragma unroll
        for (int j = 0; j < NBLOCKS / THREADS; j++)
            v += __ldcg(&g_partials[tid + j * THREADS]);
#pragma unroll
        for (int off = 16; off; off >>= 1)
            v += __shfl_xor_sync(FULL, v, off);

        __shared__ float s2[WARPS_PER_BLOCK];
        if (lane == 0) s2[tid >> 5] = v;
        __syncthreads();
        if (tid < 32) {
            float z = (tid < WARPS_PER_BLOCK) ? s2[tid] : 0.f;
#pragma unroll
            for (int off = 4; off; off >>= 1)
                z += __shfl_xor_sync(FULL, z, off);
            if (tid == 0) {
                out[0]  = z * (1.0f / (float)B_N);
                g_count = 0u;                      // reset for next graph replay
            }
        }
    }
}

extern "C" void kernel_launch(void* const* d_in, const int* in_sizes, int n_in,
                              void* d_out, int out_size)
{
    const int*   contexts = (const int*)  d_in[0];
    const int*   focus    = (const int*)  d_in[1];
    const float* wmask    = (const float*)d_in[2];
    const float* labels   = (const float*)d_in[3];
    const float* ctx_emb  = (const float*)d_in[4];
    const float* neg_emb  = (const float*)d_in[5];
    float*       out      = (float*)d_out;

    cbow_loss_kernel<<<NBLOCKS, THREADS>>>(contexts, focus, wmask, labels,
                                           ctx_emb, neg_emb, out);
}